// round 2
// baseline (speedup 1.0000x reference)
#include <cuda_runtime.h>
#include <math.h>

// Problem constants
constexpr int B_  = 4;
constexpr int T_  = 2048;
constexpr int D_  = 1024;           // complex channel count
constexpr int M1  = B_ * T_;        // 8192 rows
constexpr int N1  = 4 * D_;         // 4096  (W_in out)
constexpr int K1  = D_;             // 1024
constexpr int K2  = 2 * D_;         // 2048  (y width)
constexpr int N2  = D_;             // 1024  (final out)
constexpr int NCHUNK = 16;
constexpr int LCH = T_ / NCHUNK;    // 128 = 2^7

// Scratch (static device globals — no allocation allowed)
__device__ float g_u[(size_t)M1 * N1];      // 134 MB: u = x@W_in + b_in
__device__ float g_y[(size_t)M1 * K2];      // 67 MB : gated scan output / LN in-place
__device__ float g_cBr[B_ * NCHUNK * D_];   // chunk-local final h (real)
__device__ float g_cBi[B_ * NCHUNK * D_];
__device__ float g_carR[B_ * NCHUNK * D_];  // per-chunk initial carry (real)
__device__ float g_carI[B_ * NCHUNK * D_];

// ---------------------------------------------------------------------------
// SGEMM: C[M,N] = A[M,K] @ B[K,N] + bias[N]   (all row-major, dims % 128 == 0)
// 128x128 block tile, BK=8, 8x8 per-thread micro tile, 256 threads.
// ---------------------------------------------------------------------------
template<int BM, int BN, int BK, int TM, int TN>
__global__ __launch_bounds__(256, 2)
void sgemm_kernel(int M, int N, int K,
                  const float* __restrict__ A,
                  const float* __restrict__ Bm,
                  const float* __restrict__ bias,
                  float* __restrict__ C)
{
    const int cRow = blockIdx.y;
    const int cCol = blockIdx.x;
    const int tid  = threadIdx.x;

    __shared__ float As[BK][BM];
    __shared__ float Bs[BK][BN];

    const int threadCol = tid % (BN / TN);   // 0..15
    const int threadRow = tid / (BN / TN);   // 0..15

    // global-load mapping (each thread = one float4 of A tile, one of B tile)
    const int innerRowA = tid / (BK / 4);    // 0..127
    const int innerColA = tid % (BK / 4);    // 0..1
    const int innerRowB = tid / (BN / 4);    // 0..7
    const int innerColB = tid % (BN / 4);    // 0..31

    const float* Aptr = A + (size_t)cRow * BM * K;
    const float* Bptr = Bm + (size_t)cCol * BN;

    float acc[TM][TN];
    #pragma unroll
    for (int i = 0; i < TM; i++)
        #pragma unroll
        for (int j = 0; j < TN; j++) acc[i][j] = 0.f;

    float regM[TM], regN[TN];

    for (int k0 = 0; k0 < K; k0 += BK) {
        // A tile: 128x8, store transposed
        float4 a4 = *reinterpret_cast<const float4*>(
            Aptr + (size_t)innerRowA * K + k0 + innerColA * 4);
        As[innerColA * 4 + 0][innerRowA] = a4.x;
        As[innerColA * 4 + 1][innerRowA] = a4.y;
        As[innerColA * 4 + 2][innerRowA] = a4.z;
        As[innerColA * 4 + 3][innerRowA] = a4.w;
        // B tile: 8x128
        *reinterpret_cast<float4*>(&Bs[innerRowB][innerColB * 4]) =
            *reinterpret_cast<const float4*>(
                Bptr + (size_t)(k0 + innerRowB) * N + innerColB * 4);
        __syncthreads();

        #pragma unroll
        for (int k = 0; k < BK; k++) {
            #pragma unroll
            for (int i = 0; i < TM; i++) regM[i] = As[k][threadRow * TM + i];
            #pragma unroll
            for (int j = 0; j < TN; j++) regN[j] = Bs[k][threadCol * TN + j];
            #pragma unroll
            for (int i = 0; i < TM; i++)
                #pragma unroll
                for (int j = 0; j < TN; j++)
                    acc[i][j] += regM[i] * regN[j];
        }
        __syncthreads();
    }

    float* Cptr = C + (size_t)(cRow * BM + threadRow * TM) * N
                    + cCol * BN + threadCol * TN;
    const float* bp = bias + cCol * BN + threadCol * TN;
    #pragma unroll
    for (int i = 0; i < TM; i++) {
        #pragma unroll
        for (int j = 0; j < TN; j += 4) {
            float4 v;
            v.x = acc[i][j + 0] + bp[j + 0];
            v.y = acc[i][j + 1] + bp[j + 1];
            v.z = acc[i][j + 2] + bp[j + 2];
            v.w = acc[i][j + 3] + bp[j + 3];
            *reinterpret_cast<float4*>(Cptr + (size_t)i * N + j) = v;
        }
    }
}

// ---------------------------------------------------------------------------
// LRU scan: 3-phase chunked scan (16 chunks x 128 steps)
// ---------------------------------------------------------------------------
__device__ __forceinline__ void chan_params(const float* __restrict__ nu_log,
                                            const float* __restrict__ theta_log,
                                            const float* __restrict__ gamma_log,
                                            int d, float& fr, float& fi, float& ga)
{
    float nu = expf(-expf(nu_log[d]));
    float th = expf(theta_log[d]);
    fr = nu * cosf(th);
    fi = nu * sinf(th);
    ga = expf(gamma_log[d]);
}

// Phase 1: per-(b,chunk,d), local scan with h0 = 0; store chunk-final h.
__global__ void scan_phase1(const float* __restrict__ nu_log,
                            const float* __restrict__ theta_log,
                            const float* __restrict__ gamma_log)
{
    int idx = blockIdx.x * blockDim.x + threadIdx.x;   // b*NCHUNK*D + c*D + d
    int d = idx % D_;
    int c = (idx / D_) % NCHUNK;
    int b = idx / (D_ * NCHUNK);

    float fr, fi, ga;
    chan_params(nu_log, theta_log, gamma_log, d, fr, fi, ga);

    const float* up = g_u + (size_t)(b * T_ + c * LCH) * N1;
    float hr = 0.f, hi = 0.f;
    for (int t = 0; t < LCH; t++) {
        float vr = ga * up[(size_t)t * N1 + d];
        float vi = ga * up[(size_t)t * N1 + D_ + d];
        float nr = fr * hr - fi * hi + vr;
        float ni = fr * hi + fi * hr + vi;
        hr = nr; hi = ni;
    }
    g_cBr[idx] = hr;
    g_cBi[idx] = hi;
}

// Phase 2: per-(b,d), combine chunk results sequentially; store carry per chunk.
__global__ void scan_phase2(const float* __restrict__ nu_log,
                            const float* __restrict__ theta_log)
{
    int idx = blockIdx.x * blockDim.x + threadIdx.x;   // b*D + d
    int d = idx % D_;
    int b = idx / D_;

    float nu = expf(-expf(nu_log[d]));
    float th = expf(theta_log[d]);
    float ar = nu * cosf(th);
    float ai = nu * sinf(th);
    // f^128 via 7 complex squarings
    #pragma unroll
    for (int s = 0; s < 7; s++) {
        float nr = ar * ar - ai * ai;
        float ni = 2.f * ar * ai;
        ar = nr; ai = ni;
    }

    float cr = 0.f, ci = 0.f;
    for (int c = 0; c < NCHUNK; c++) {
        int o = (b * NCHUNK + c) * D_ + d;
        g_carR[o] = cr;
        g_carI[o] = ci;
        float br = g_cBr[o], bi = g_cBi[o];
        float nr = ar * cr - ai * ci + br;
        float ni = ar * ci + ai * cr + bi;
        cr = nr; ci = ni;
    }
}

// Phase 3: re-scan each chunk starting from its carry, apply SiLU gate, write y.
__global__ void scan_phase3(const float* __restrict__ nu_log,
                            const float* __restrict__ theta_log,
                            const float* __restrict__ gamma_log)
{
    int idx = blockIdx.x * blockDim.x + threadIdx.x;   // b*NCHUNK*D + c*D + d
    int d = idx % D_;
    int c = (idx / D_) % NCHUNK;
    int b = idx / (D_ * NCHUNK);

    float fr, fi, ga;
    chan_params(nu_log, theta_log, gamma_log, d, fr, fi, ga);

    int o = (b * NCHUNK + c) * D_ + d;
    float hr = g_carR[o], hi = g_carI[o];

    const float* up = g_u + (size_t)(b * T_ + c * LCH) * N1;
    float*       yp = g_y + (size_t)(b * T_ + c * LCH) * K2;

    for (int t = 0; t < LCH; t++) {
        float vr = ga * up[(size_t)t * N1 + d];
        float vi = ga * up[(size_t)t * N1 + D_ + d];
        float o1 = up[(size_t)t * N1 + 2 * D_ + d];
        float o2 = up[(size_t)t * N1 + 3 * D_ + d];
        float nr = fr * hr - fi * hi + vr;
        float ni = fr * hi + fi * hr + vi;
        hr = nr; hi = ni;
        float s1 = o1 / (1.f + expf(-o1));
        float s2 = o2 / (1.f + expf(-o2));
        yp[(size_t)t * K2 + d]       = hr * s1;
        yp[(size_t)t * K2 + D_ + d]  = hi * s2;
    }
}

// ---------------------------------------------------------------------------
// LayerNorm over last dim (2048), in place on g_y. One block per row.
// ---------------------------------------------------------------------------
__global__ void ln_kernel(const float* __restrict__ ln_w,
                          const float* __restrict__ ln_b)
{
    const int row = blockIdx.x;
    float* yp = g_y + (size_t)row * K2;

    float lsum = 0.f, lsq = 0.f;
    for (int i = threadIdx.x; i < K2; i += blockDim.x) {
        float v = yp[i];
        lsum += v;
        lsq  += v * v;
    }
    // warp reduce
    #pragma unroll
    for (int off = 16; off > 0; off >>= 1) {
        lsum += __shfl_xor_sync(0xFFFFFFFF, lsum, off);
        lsq  += __shfl_xor_sync(0xFFFFFFFF, lsq,  off);
    }
    __shared__ float s1[8], s2[8];
    int wid = threadIdx.x >> 5, lane = threadIdx.x & 31;
    if (lane == 0) { s1[wid] = lsum; s2[wid] = lsq; }
    __syncthreads();
    if (wid == 0) {
        float a = (lane < 8) ? s1[lane] : 0.f;
        float b = (lane < 8) ? s2[lane] : 0.f;
        #pragma unroll
        for (int off = 4; off > 0; off >>= 1) {
            a += __shfl_xor_sync(0xFFFFFFFF, a, off);
            b += __shfl_xor_sync(0xFFFFFFFF, b, off);
        }
        if (lane == 0) { s1[0] = a; s2[0] = b; }
    }
    __syncthreads();
    float mean = s1[0] / K2;
    float var  = s2[0] / K2 - mean * mean;
    float inv  = rsqrtf(var + 1e-5f);

    for (int i = threadIdx.x; i < K2; i += blockDim.x) {
        yp[i] = (yp[i] - mean) * inv * ln_w[i] + ln_b[i];
    }
}

// ---------------------------------------------------------------------------
// Launch
// ---------------------------------------------------------------------------
extern "C" void kernel_launch(void* const* d_in, const int* in_sizes, int n_in,
                              void* d_out, int out_size)
{
    const float* x         = (const float*)d_in[0];
    const float* W_in      = (const float*)d_in[1];
    const float* b_in      = (const float*)d_in[2];
    const float* nu_log    = (const float*)d_in[3];
    const float* theta_log = (const float*)d_in[4];
    const float* gamma_log = (const float*)d_in[5];
    const float* ln_w      = (const float*)d_in[6];
    const float* ln_b      = (const float*)d_in[7];
    const float* W_out     = (const float*)d_in[8];
    const float* b_out     = (const float*)d_in[9];
    float* out = (float*)d_out;

    float *u_ptr, *y_ptr;
    cudaGetSymbolAddress((void**)&u_ptr, g_u);
    cudaGetSymbolAddress((void**)&y_ptr, g_y);

    // GEMM1: u = x @ W_in + b_in     [8192,1024]@[1024,4096]
    {
        dim3 grid(N1 / 128, M1 / 128);
        sgemm_kernel<128, 128, 8, 8, 8><<<grid, 256>>>(M1, N1, K1, x, W_in, b_in, u_ptr);
    }
    // Scan (3-phase)
    {
        int total = B_ * NCHUNK * D_;
        scan_phase1<<<total / 256, 256>>>(nu_log, theta_log, gamma_log);
        scan_phase2<<<(B_ * D_) / 256, 256>>>(nu_log, theta_log);
        scan_phase3<<<total / 256, 256>>>(nu_log, theta_log, gamma_log);
    }
    // LayerNorm in-place on g_y
    ln_kernel<<<M1, 256>>>(ln_w, ln_b);

    // GEMM2: out = y @ W_out + b_out  [8192,2048]@[2048,1024]
    {
        dim3 grid(N2 / 128, M1 / 128);
        sgemm_kernel<128, 128, 8, 8, 8><<<grid, 256>>>(M1, N2, K2, y_ptr, W_out, b_out, out);
    }
}

// round 4
// speedup vs baseline: 2.5614x; 2.5614x over previous
#include <cuda_runtime.h>
#include <cuda_bf16.h>
#include <math.h>
#include <stdint.h>

// ---------------------------------------------------------------------------
// Problem constants
// ---------------------------------------------------------------------------
constexpr int B_  = 4;
constexpr int T_  = 2048;
constexpr int D_  = 1024;
constexpr int M1  = B_ * T_;        // 8192
constexpr int N1  = 4 * D_;         // 4096
constexpr int K1  = D_;             // 1024
constexpr int K2  = 2 * D_;         // 2048
constexpr int N2  = D_;             // 1024
constexpr int NCHUNK = 16;
constexpr int LCH = T_ / NCHUNK;    // 128

// ---------------------------------------------------------------------------
// Scratch (static device globals — no allocation allowed)
// ---------------------------------------------------------------------------
__device__ float g_u[(size_t)M1 * N1];
__device__ float g_y[(size_t)M1 * K2];
__device__ float g_cBr[B_ * NCHUNK * D_];
__device__ float g_cBi[B_ * NCHUNK * D_];
__device__ float g_carR[B_ * NCHUNK * D_];
__device__ float g_carI[B_ * NCHUNK * D_];

__device__ __nv_bfloat16 g_xh[(size_t)M1 * K1];
__device__ __nv_bfloat16 g_xl[(size_t)M1 * K1];
__device__ __nv_bfloat16 g_w1h[(size_t)N1 * K1];   // W_in^T  [4096,1024]
__device__ __nv_bfloat16 g_w1l[(size_t)N1 * K1];
__device__ __nv_bfloat16 g_yh[(size_t)M1 * K2];
__device__ __nv_bfloat16 g_yl[(size_t)M1 * K2];
__device__ __nv_bfloat16 g_w2h[(size_t)N2 * K2];   // W_out^T [1024,2048]
__device__ __nv_bfloat16 g_w2l[(size_t)N2 * K2];

// ---------------------------------------------------------------------------
// PTX helpers
// ---------------------------------------------------------------------------
__device__ __forceinline__ uint32_t smem_u32(const void* p) {
    uint32_t a;
    asm("{ .reg .u64 t; cvta.to.shared.u64 t, %1; cvt.u32.u64 %0, t; }"
        : "=r"(a) : "l"(p));
    return a;
}

__device__ __forceinline__ void cp16(uint32_t dst, const void* src) {
    asm volatile("cp.async.cg.shared.global [%0], [%1], 16;\n" :: "r"(dst), "l"(src) : "memory");
}
#define CP_COMMIT() asm volatile("cp.async.commit_group;" ::: "memory")

__device__ __forceinline__ void ldm_x4(uint32_t* r, uint32_t addr) {
    asm volatile("ldmatrix.sync.aligned.m8n8.x4.shared.b16 {%0,%1,%2,%3}, [%4];"
                 : "=r"(r[0]), "=r"(r[1]), "=r"(r[2]), "=r"(r[3]) : "r"(addr));
}

__device__ __forceinline__ void mma_bf16(float* d, const uint32_t* a, uint32_t b0, uint32_t b1) {
    asm volatile(
        "mma.sync.aligned.m16n8k16.row.col.f32.bf16.bf16.f32 "
        "{%0,%1,%2,%3}, {%4,%5,%6,%7}, {%8,%9}, {%0,%1,%2,%3};"
        : "+f"(d[0]), "+f"(d[1]), "+f"(d[2]), "+f"(d[3])
        : "r"(a[0]), "r"(a[1]), "r"(a[2]), "r"(a[3]), "r"(b0), "r"(b1));
}

// ---------------------------------------------------------------------------
// bf16-split MMA GEMM: C[M,N] = A[M,K] @ Bt[N,K]^T + bias
// A hi/lo bf16 [M,K]; B hi/lo bf16 [N,K] (i.e., B col-major for mma row.col).
// 128x128 tile, BK=32, 8 warps (2m x 4n, warp tile 64x32), double-buffered.
// SMEM: per stage  Ah@0 Al@8K Bh@16K Bl@24K (each 128 rows x 64B, XOR-swizzled)
// ---------------------------------------------------------------------------
constexpr int GEMM_SMEM = 2 * 32768;   // 64 KB

__device__ __forceinline__ uint32_t sw_off(int row, int kch) {
    return (uint32_t)(row * 64 + ((kch ^ ((row >> 1) & 3)) << 4));
}

__global__ __launch_bounds__(256, 1)
void mma_gemm(int M, int N, int K,
              const __nv_bfloat16* __restrict__ Ah, const __nv_bfloat16* __restrict__ Al,
              const __nv_bfloat16* __restrict__ Bh, const __nv_bfloat16* __restrict__ Bl,
              const float* __restrict__ bias, float* __restrict__ C)
{
    extern __shared__ char smem[];
    const uint32_t sb = smem_u32(smem);
    const int tid  = threadIdx.x;
    const int lane = tid & 31;
    const int wid  = tid >> 5;
    const int wm   = wid & 1;        // 2 warps along M
    const int wn   = wid >> 1;       // 4 warps along N

    const size_t arow0 = (size_t)blockIdx.y * 128;
    const size_t brow0 = (size_t)blockIdx.x * 128;
    const int S = K / 32;

    float acc[4][4][4];
    #pragma unroll
    for (int i = 0; i < 4; i++)
        #pragma unroll
        for (int j = 0; j < 4; j++)
            #pragma unroll
            for (int k = 0; k < 4; k++) acc[i][j][k] = 0.f;

    // per-thread load coordinates: 2 x 16B chunks per tile per stage
    const int r0a = (tid + 0)   >> 2, c0a = (tid + 0)   & 3;
    const int r1a = (tid + 256) >> 2, c1a = (tid + 256) & 3;

    auto load_stage = [&](int s, int buf) {
        const uint32_t st = sb + (uint32_t)buf * 32768u;
        const int k0 = s * 32;
        // Ah
        cp16(st +     sw_off(r0a, c0a), Ah + (arow0 + r0a) * (size_t)K + k0 + c0a * 8);
        cp16(st +     sw_off(r1a, c1a), Ah + (arow0 + r1a) * (size_t)K + k0 + c1a * 8);
        // Al
        cp16(st + 8192u  + sw_off(r0a, c0a), Al + (arow0 + r0a) * (size_t)K + k0 + c0a * 8);
        cp16(st + 8192u  + sw_off(r1a, c1a), Al + (arow0 + r1a) * (size_t)K + k0 + c1a * 8);
        // Bh
        cp16(st + 16384u + sw_off(r0a, c0a), Bh + (brow0 + r0a) * (size_t)K + k0 + c0a * 8);
        cp16(st + 16384u + sw_off(r1a, c1a), Bh + (brow0 + r1a) * (size_t)K + k0 + c1a * 8);
        // Bl
        cp16(st + 24576u + sw_off(r0a, c0a), Bl + (brow0 + r0a) * (size_t)K + k0 + c0a * 8);
        cp16(st + 24576u + sw_off(r1a, c1a), Bl + (brow0 + r1a) * (size_t)K + k0 + c1a * 8);
    };

    // ldmatrix lane sub-coordinates
    const int sub = lane >> 3;       // which 8x8 matrix this lane addresses
    const int r8  = lane & 7;

    load_stage(0, 0);
    CP_COMMIT();

    for (int s = 0; s < S; s++) {
        if (s + 1 < S) {
            load_stage(s + 1, (s + 1) & 1);
            CP_COMMIT();
            asm volatile("cp.async.wait_group 1;" ::: "memory");
        } else {
            asm volatile("cp.async.wait_group 0;" ::: "memory");
        }
        __syncthreads();

        const uint32_t st = sb + (uint32_t)(s & 1) * 32768u;
        #pragma unroll
        for (int ks = 0; ks < 2; ks++) {
            uint32_t aH[4][4], aL[4][4], bH[2][4], bL[2][4];
            #pragma unroll
            for (int mi = 0; mi < 4; mi++) {
                const int mrow = wm * 64 + mi * 16 + (sub & 1) * 8 + r8;
                const int kch  = ks * 2 + (sub >> 1);
                ldm_x4(aH[mi], st +        sw_off(mrow, kch));
                ldm_x4(aL[mi], st + 8192u + sw_off(mrow, kch));
            }
            #pragma unroll
            for (int np = 0; np < 2; np++) {
                const int nrow = wn * 32 + np * 16 + (sub >> 1) * 8 + r8;
                const int kch  = ks * 2 + (sub & 1);
                ldm_x4(bH[np], st + 16384u + sw_off(nrow, kch));
                ldm_x4(bL[np], st + 24576u + sw_off(nrow, kch));
            }
            #pragma unroll
            for (int mi = 0; mi < 4; mi++) {
                #pragma unroll
                for (int ni = 0; ni < 4; ni++) {
                    const int np = ni >> 1, hh = (ni & 1) * 2;
                    mma_bf16(acc[mi][ni], aH[mi], bH[np][hh], bH[np][hh + 1]);
                    mma_bf16(acc[mi][ni], aH[mi], bL[np][hh], bL[np][hh + 1]);
                    mma_bf16(acc[mi][ni], aL[mi], bH[np][hh], bH[np][hh + 1]);
                }
            }
        }
        __syncthreads();
    }

    // Epilogue: accumulators -> C with bias (float2 stores)
    #pragma unroll
    for (int mi = 0; mi < 4; mi++) {
        const size_t r0 = arow0 + wm * 64 + mi * 16 + (lane >> 2);
        #pragma unroll
        for (int ni = 0; ni < 4; ni++) {
            const int c = blockIdx.x * 128 + wn * 32 + ni * 8 + (lane & 3) * 2;
            const float b0 = bias[c], b1 = bias[c + 1];
            float2 v0 = make_float2(acc[mi][ni][0] + b0, acc[mi][ni][1] + b1);
            float2 v1 = make_float2(acc[mi][ni][2] + b0, acc[mi][ni][3] + b1);
            *reinterpret_cast<float2*>(C + r0 * (size_t)N + c)       = v0;
            *reinterpret_cast<float2*>(C + (r0 + 8) * (size_t)N + c) = v1;
        }
    }
}

// ---------------------------------------------------------------------------
// fp32 -> bf16 hi/lo split (elementwise)
// ---------------------------------------------------------------------------
__global__ void split_rows(const float* __restrict__ X,
                           __nv_bfloat16* __restrict__ Xh,
                           __nv_bfloat16* __restrict__ Xl, size_t n)
{
    size_t i = ((size_t)blockIdx.x * blockDim.x + threadIdx.x) * 4;
    if (i >= n) return;
    float4 v = *reinterpret_cast<const float4*>(X + i);
    __nv_bfloat16 h0 = __float2bfloat16_rn(v.x);
    __nv_bfloat16 h1 = __float2bfloat16_rn(v.y);
    __nv_bfloat16 h2 = __float2bfloat16_rn(v.z);
    __nv_bfloat16 h3 = __float2bfloat16_rn(v.w);
    __nv_bfloat162 hA = __nv_bfloat162(h0, h1), hB = __nv_bfloat162(h2, h3);
    __nv_bfloat162 lA = __nv_bfloat162(__float2bfloat16_rn(v.x - __bfloat162float(h0)),
                                       __float2bfloat16_rn(v.y - __bfloat162float(h1)));
    __nv_bfloat162 lB = __nv_bfloat162(__float2bfloat16_rn(v.z - __bfloat162float(h2)),
                                       __float2bfloat16_rn(v.w - __bfloat162float(h3)));
    *reinterpret_cast<__nv_bfloat162*>(Xh + i)     = hA;
    *reinterpret_cast<__nv_bfloat162*>(Xh + i + 2) = hB;
    *reinterpret_cast<__nv_bfloat162*>(Xl + i)     = lA;
    *reinterpret_cast<__nv_bfloat162*>(Xl + i + 2) = lB;
}

// ---------------------------------------------------------------------------
// W[K,N] -> T[N,K] transpose + bf16 hi/lo split
// ---------------------------------------------------------------------------
__global__ void transpose_split(const float* __restrict__ W, int K, int N,
                                __nv_bfloat16* __restrict__ Th,
                                __nv_bfloat16* __restrict__ Tl)
{
    __shared__ float tile[32][33];
    int n0 = blockIdx.x * 32, k0 = blockIdx.y * 32;
    int tx = threadIdx.x, ty = threadIdx.y;    // 32 x 8
    #pragma unroll
    for (int i = 0; i < 32; i += 8)
        tile[ty + i][tx] = W[(size_t)(k0 + ty + i) * N + n0 + tx];
    __syncthreads();
    #pragma unroll
    for (int i = 0; i < 32; i += 8) {
        int nn = ty + i, kk = tx;
        float v = tile[kk][nn];
        __nv_bfloat16 h = __float2bfloat16_rn(v);
        Th[(size_t)(n0 + nn) * K + k0 + kk] = h;
        Tl[(size_t)(n0 + nn) * K + k0 + kk] = __float2bfloat16_rn(v - __bfloat162float(h));
    }
}

// ---------------------------------------------------------------------------
// LRU scan (3-phase chunked)
// ---------------------------------------------------------------------------
__device__ __forceinline__ void chan_params(const float* __restrict__ nu_log,
                                            const float* __restrict__ theta_log,
                                            const float* __restrict__ gamma_log,
                                            int d, float& fr, float& fi, float& ga)
{
    float nu = expf(-expf(nu_log[d]));
    float th = expf(theta_log[d]);
    fr = nu * cosf(th);
    fi = nu * sinf(th);
    ga = expf(gamma_log[d]);
}

__global__ void scan_phase1(const float* __restrict__ nu_log,
                            const float* __restrict__ theta_log,
                            const float* __restrict__ gamma_log)
{
    int idx = blockIdx.x * blockDim.x + threadIdx.x;
    int d = idx % D_;
    int c = (idx / D_) % NCHUNK;
    int b = idx / (D_ * NCHUNK);

    float fr, fi, ga;
    chan_params(nu_log, theta_log, gamma_log, d, fr, fi, ga);

    const float* up = g_u + (size_t)(b * T_ + c * LCH) * N1;
    float hr = 0.f, hi = 0.f;
    for (int t = 0; t < LCH; t++) {
        float vr = ga * up[(size_t)t * N1 + d];
        float vi = ga * up[(size_t)t * N1 + D_ + d];
        float nr = fr * hr - fi * hi + vr;
        float ni = fr * hi + fi * hr + vi;
        hr = nr; hi = ni;
    }
    g_cBr[idx] = hr;
    g_cBi[idx] = hi;
}

__global__ void scan_phase2(const float* __restrict__ nu_log,
                            const float* __restrict__ theta_log)
{
    int idx = blockIdx.x * blockDim.x + threadIdx.x;
    int d = idx % D_;
    int b = idx / D_;

    float nu = expf(-expf(nu_log[d]));
    float th = expf(theta_log[d]);
    float ar = nu * cosf(th);
    float ai = nu * sinf(th);
    #pragma unroll
    for (int s = 0; s < 7; s++) {
        float nr = ar * ar - ai * ai;
        float ni = 2.f * ar * ai;
        ar = nr; ai = ni;
    }

    float cr = 0.f, ci = 0.f;
    for (int c = 0; c < NCHUNK; c++) {
        int o = (b * NCHUNK + c) * D_ + d;
        g_carR[o] = cr;
        g_carI[o] = ci;
        float br = g_cBr[o], bi = g_cBi[o];
        float nr = ar * cr - ai * ci + br;
        float ni = ar * ci + ai * cr + bi;
        cr = nr; ci = ni;
    }
}

__global__ void scan_phase3(const float* __restrict__ nu_log,
                            const float* __restrict__ theta_log,
                            const float* __restrict__ gamma_log)
{
    int idx = blockIdx.x * blockDim.x + threadIdx.x;
    int d = idx % D_;
    int c = (idx / D_) % NCHUNK;
    int b = idx / (D_ * NCHUNK);

    float fr, fi, ga;
    chan_params(nu_log, theta_log, gamma_log, d, fr, fi, ga);

    int o = (b * NCHUNK + c) * D_ + d;
    float hr = g_carR[o], hi = g_carI[o];

    const float* up = g_u + (size_t)(b * T_ + c * LCH) * N1;
    float*       yp = g_y + (size_t)(b * T_ + c * LCH) * K2;

    for (int t = 0; t < LCH; t++) {
        float vr = ga * up[(size_t)t * N1 + d];
        float vi = ga * up[(size_t)t * N1 + D_ + d];
        float o1 = up[(size_t)t * N1 + 2 * D_ + d];
        float o2 = up[(size_t)t * N1 + 3 * D_ + d];
        float nr = fr * hr - fi * hi + vr;
        float ni = fr * hi + fi * hr + vi;
        hr = nr; hi = ni;
        float s1 = o1 / (1.f + expf(-o1));
        float s2 = o2 / (1.f + expf(-o2));
        yp[(size_t)t * K2 + d]       = hr * s1;
        yp[(size_t)t * K2 + D_ + d]  = hi * s2;
    }
}

// ---------------------------------------------------------------------------
// LayerNorm(2048) fused with bf16 hi/lo split: g_y -> g_yh/g_yl
// ---------------------------------------------------------------------------
__global__ void ln_split_kernel(const float* __restrict__ ln_w,
                                const float* __restrict__ ln_b)
{
    const int row = blockIdx.x;
    const float* yp = g_y + (size_t)row * K2;
    __nv_bfloat16* yh = g_yh + (size_t)row * K2;
    __nv_bfloat16* yl = g_yl + (size_t)row * K2;

    float lsum = 0.f, lsq = 0.f;
    for (int i = threadIdx.x; i < K2; i += blockDim.x) {
        float v = yp[i];
        lsum += v;
        lsq  += v * v;
    }
    #pragma unroll
    for (int off = 16; off > 0; off >>= 1) {
        lsum += __shfl_xor_sync(0xFFFFFFFF, lsum, off);
        lsq  += __shfl_xor_sync(0xFFFFFFFF, lsq,  off);
    }
    __shared__ float s1[8], s2[8];
    int wid = threadIdx.x >> 5, lane = threadIdx.x & 31;
    if (lane == 0) { s1[wid] = lsum; s2[wid] = lsq; }
    __syncthreads();
    if (wid == 0) {
        float a = (lane < 8) ? s1[lane] : 0.f;
        float b = (lane < 8) ? s2[lane] : 0.f;
        #pragma unroll
        for (int off = 4; off > 0; off >>= 1) {
            a += __shfl_xor_sync(0xFFFFFFFF, a, off);
            b += __shfl_xor_sync(0xFFFFFFFF, b, off);
        }
        if (lane == 0) { s1[0] = a; s2[0] = b; }
    }
    __syncthreads();
    float mean = s1[0] / K2;
    float var  = s2[0] / K2 - mean * mean;
    float inv  = rsqrtf(var + 1e-5f);

    for (int i = threadIdx.x; i < K2; i += blockDim.x) {
        float v = (yp[i] - mean) * inv * ln_w[i] + ln_b[i];
        __nv_bfloat16 h = __float2bfloat16_rn(v);
        yh[i] = h;
        yl[i] = __float2bfloat16_rn(v - __bfloat162float(h));
    }
}

// ---------------------------------------------------------------------------
// Launch
// ---------------------------------------------------------------------------
extern "C" void kernel_launch(void* const* d_in, const int* in_sizes, int n_in,
                              void* d_out, int out_size)
{
    const float* x         = (const float*)d_in[0];
    const float* W_in      = (const float*)d_in[1];
    const float* b_in      = (const float*)d_in[2];
    const float* nu_log    = (const float*)d_in[3];
    const float* theta_log = (const float*)d_in[4];
    const float* gamma_log = (const float*)d_in[5];
    const float* ln_w      = (const float*)d_in[6];
    const float* ln_b      = (const float*)d_in[7];
    const float* W_out     = (const float*)d_in[8];
    const float* b_out     = (const float*)d_in[9];
    float* out = (float*)d_out;

    float *u_ptr;
    cudaGetSymbolAddress((void**)&u_ptr, g_u);
    __nv_bfloat16 *xh, *xl, *w1h, *w1l, *yh, *yl, *w2h, *w2l;
    cudaGetSymbolAddress((void**)&xh,  g_xh);
    cudaGetSymbolAddress((void**)&xl,  g_xl);
    cudaGetSymbolAddress((void**)&w1h, g_w1h);
    cudaGetSymbolAddress((void**)&w1l, g_w1l);
    cudaGetSymbolAddress((void**)&yh,  g_yh);
    cudaGetSymbolAddress((void**)&yl,  g_yl);
    cudaGetSymbolAddress((void**)&w2h, g_w2h);
    cudaGetSymbolAddress((void**)&w2l, g_w2l);

    cudaFuncSetAttribute(mma_gemm, cudaFuncAttributeMaxDynamicSharedMemorySize, GEMM_SMEM);

    // operand prep for GEMM1
    {
        size_t n = (size_t)M1 * K1;
        split_rows<<<(unsigned)((n / 4 + 255) / 256), 256>>>(x, xh, xl, n);
        dim3 g(N1 / 32, K1 / 32);
        transpose_split<<<g, dim3(32, 8)>>>(W_in, K1, N1, w1h, w1l);
    }
    // GEMM1: u = x @ W_in + b_in
    {
        dim3 grid(N1 / 128, M1 / 128);
        mma_gemm<<<grid, 256, GEMM_SMEM>>>(M1, N1, K1, xh, xl, w1h, w1l, b_in, u_ptr);
    }
    // Scan (3-phase)
    {
        int total = B_ * NCHUNK * D_;
        scan_phase1<<<total / 256, 256>>>(nu_log, theta_log, gamma_log);
        scan_phase2<<<(B_ * D_) / 256, 256>>>(nu_log, theta_log);
        scan_phase3<<<total / 256, 256>>>(nu_log, theta_log, gamma_log);
    }
    // LayerNorm + bf16 split fused
    ln_split_kernel<<<M1, 256>>>(ln_w, ln_b);

    // operand prep for GEMM2 (weights only; y already split)
    {
        dim3 g(N2 / 32, K2 / 32);
        transpose_split<<<g, dim3(32, 8)>>>(W_out, K2, N2, w2h, w2l);
    }
    // GEMM2: out = y @ W_out + b_out
    {
        dim3 grid(N2 / 128, M1 / 128);
        mma_gemm<<<grid, 256, GEMM_SMEM>>>(M1, N2, K2, yh, yl, w2h, w2l, b_out, out);
    }
}

// round 7
// speedup vs baseline: 2.7218x; 1.0626x over previous
#include <cuda_runtime.h>
#include <cuda_bf16.h>
#include <math.h>
#include <stdint.h>

// ---------------------------------------------------------------------------
// Problem constants
// ---------------------------------------------------------------------------
constexpr int B_  = 4;
constexpr int T_  = 2048;
constexpr int D_  = 1024;
constexpr int M1  = B_ * T_;        // 8192
constexpr int N1  = 4 * D_;         // 4096
constexpr int K1  = D_;             // 1024
constexpr int K2  = 2 * D_;         // 2048
constexpr int N2  = D_;             // 1024
constexpr int NCHUNK = 32;
constexpr int LCH = T_ / NCHUNK;    // 64

// ---------------------------------------------------------------------------
// Scratch (static device globals — no allocation allowed)
// ---------------------------------------------------------------------------
__device__ float g_u[(size_t)M1 * N1];
__device__ float g_y[(size_t)M1 * K2];
__device__ float g_cBr[B_ * NCHUNK * D_];
__device__ float g_cBi[B_ * NCHUNK * D_];
__device__ float g_carR[B_ * NCHUNK * D_];
__device__ float g_carI[B_ * NCHUNK * D_];

__device__ __nv_bfloat16 g_xh[(size_t)M1 * K1];
__device__ __nv_bfloat16 g_xl[(size_t)M1 * K1];
__device__ __nv_bfloat16 g_w1h[(size_t)N1 * K1];   // W_in^T  [4096,1024]
__device__ __nv_bfloat16 g_w1l[(size_t)N1 * K1];
__device__ __nv_bfloat16 g_yh[(size_t)M1 * K2];
__device__ __nv_bfloat16 g_yl[(size_t)M1 * K2];
__device__ __nv_bfloat16 g_w2h[(size_t)N2 * K2];   // W_out^T [1024,2048]
__device__ __nv_bfloat16 g_w2l[(size_t)N2 * K2];

// ---------------------------------------------------------------------------
// PTX helpers
// ---------------------------------------------------------------------------
__device__ __forceinline__ uint32_t smem_u32(const void* p) {
    uint32_t a;
    asm("{ .reg .u64 t; cvta.to.shared.u64 t, %1; cvt.u32.u64 %0, t; }"
        : "=r"(a) : "l"(p));
    return a;
}

__device__ __forceinline__ void cp16(uint32_t dst, const void* src) {
    asm volatile("cp.async.cg.shared.global [%0], [%1], 16;\n" :: "r"(dst), "l"(src) : "memory");
}
#define CP_COMMIT() asm volatile("cp.async.commit_group;" ::: "memory")

__device__ __forceinline__ void ldm_x4(uint32_t* r, uint32_t addr) {
    asm volatile("ldmatrix.sync.aligned.m8n8.x4.shared.b16 {%0,%1,%2,%3}, [%4];"
                 : "=r"(r[0]), "=r"(r[1]), "=r"(r[2]), "=r"(r[3]) : "r"(addr));
}

__device__ __forceinline__ void mma_bf16(float* d, const uint32_t* a, uint32_t b0, uint32_t b1) {
    asm volatile(
        "mma.sync.aligned.m16n8k16.row.col.f32.bf16.bf16.f32 "
        "{%0,%1,%2,%3}, {%4,%5,%6,%7}, {%8,%9}, {%0,%1,%2,%3};"
        : "+f"(d[0]), "+f"(d[1]), "+f"(d[2]), "+f"(d[3])
        : "r"(a[0]), "r"(a[1]), "r"(a[2]), "r"(a[3]), "r"(b0), "r"(b1));
}

// ---------------------------------------------------------------------------
// bf16-split MMA GEMM: C[M,N] = A[M,K] @ Bt[N,K]^T + bias
// 128x128 tile, BK=32, 8 warps (2m x 4n, warp tile 64x32).
// 4-stage cp.async ring, ONE __syncthreads per stage, grid swizzled.
// SMEM slot (32KB): Ah@0 Al@8K Bh@16K Bl@24K (each 128 rows x 64B, XOR swizzle)
// ---------------------------------------------------------------------------
constexpr int NSTAGE    = 4;
constexpr int SLOT      = 32768;
constexpr int GEMM_SMEM = NSTAGE * SLOT;   // 128 KB

__device__ __forceinline__ uint32_t sw_off(int row, int kch) {
    return (uint32_t)(row * 64 + ((kch ^ ((row >> 1) & 3)) << 4));
}

__global__ __launch_bounds__(256, 1)
void mma_gemm(int M, int N, int K,
              const __nv_bfloat16* __restrict__ Ah, const __nv_bfloat16* __restrict__ Al,
              const __nv_bfloat16* __restrict__ Bh, const __nv_bfloat16* __restrict__ Bl,
              const float* __restrict__ bias, float* __restrict__ C)
{
    extern __shared__ char smem[];
    const uint32_t sb = smem_u32(smem);
    const int tid  = threadIdx.x;
    const int lane = tid & 31;
    const int wid  = tid >> 5;
    const int wm   = wid & 1;
    const int wn   = wid >> 1;

    // grid swizzle: 8-row bands, column-minor inside band
    const int nbx  = N >> 7;
    const int lin  = blockIdx.x;
    const int band = lin / (8 * nbx);
    const int rem  = lin % (8 * nbx);
    const int by   = band * 8 + (rem & 7);
    const int bx   = rem >> 3;

    const size_t arow0 = (size_t)by * 128;
    const size_t brow0 = (size_t)bx * 128;
    const int S = K / 32;

    float acc[4][4][4];
    #pragma unroll
    for (int i = 0; i < 4; i++)
        #pragma unroll
        for (int j = 0; j < 4; j++)
            #pragma unroll
            for (int k = 0; k < 4; k++) acc[i][j][k] = 0.f;

    const int r0a = (tid + 0)   >> 2, c0a = (tid + 0)   & 3;
    const int r1a = (tid + 256) >> 2, c1a = (tid + 256) & 3;

    auto load_stage = [&](int s, int slot) {
        const uint32_t st = sb + (uint32_t)slot * (uint32_t)SLOT;
        const int k0 = s * 32;
        cp16(st +          sw_off(r0a, c0a), Ah + (arow0 + r0a) * (size_t)K + k0 + c0a * 8);
        cp16(st +          sw_off(r1a, c1a), Ah + (arow0 + r1a) * (size_t)K + k0 + c1a * 8);
        cp16(st + 8192u  + sw_off(r0a, c0a), Al + (arow0 + r0a) * (size_t)K + k0 + c0a * 8);
        cp16(st + 8192u  + sw_off(r1a, c1a), Al + (arow0 + r1a) * (size_t)K + k0 + c1a * 8);
        cp16(st + 16384u + sw_off(r0a, c0a), Bh + (brow0 + r0a) * (size_t)K + k0 + c0a * 8);
        cp16(st + 16384u + sw_off(r1a, c1a), Bh + (brow0 + r1a) * (size_t)K + k0 + c1a * 8);
        cp16(st + 24576u + sw_off(r0a, c0a), Bl + (brow0 + r0a) * (size_t)K + k0 + c0a * 8);
        cp16(st + 24576u + sw_off(r1a, c1a), Bl + (brow0 + r1a) * (size_t)K + k0 + c1a * 8);
    };

    const int sub = lane >> 3;
    const int r8  = lane & 7;

    // preload first 3 stages (one commit group each)
    load_stage(0, 0); CP_COMMIT();
    load_stage(1, 1); CP_COMMIT();
    load_stage(2, 2); CP_COMMIT();

    for (int s = 0; s < S; s++) {
        // exactly one group is committed per iteration (possibly empty), so
        // wait_group 2 == "stage s resident"
        asm volatile("cp.async.wait_group 2;" ::: "memory");
        __syncthreads();

        if (s + 3 < S) load_stage(s + 3, (s + 3) & 3);
        CP_COMMIT();

        const uint32_t st = sb + (uint32_t)(s & 3) * (uint32_t)SLOT;
        #pragma unroll
        for (int ks = 0; ks < 2; ks++) {
            uint32_t aH[4][4], aL[4][4], bH[2][4], bL[2][4];
            #pragma unroll
            for (int mi = 0; mi < 4; mi++) {
                const int mrow = wm * 64 + mi * 16 + (sub & 1) * 8 + r8;
                const int kch  = ks * 2 + (sub >> 1);
                ldm_x4(aH[mi], st +         sw_off(mrow, kch));
                ldm_x4(aL[mi], st + 8192u + sw_off(mrow, kch));
            }
            #pragma unroll
            for (int np = 0; np < 2; np++) {
                const int nrow = wn * 32 + np * 16 + (sub >> 1) * 8 + r8;
                const int kch  = ks * 2 + (sub & 1);
                ldm_x4(bH[np], st + 16384u + sw_off(nrow, kch));
                ldm_x4(bL[np], st + 24576u + sw_off(nrow, kch));
            }
            #pragma unroll
            for (int mi = 0; mi < 4; mi++) {
                #pragma unroll
                for (int ni = 0; ni < 4; ni++) {
                    const int np = ni >> 1, hh = (ni & 1) * 2;
                    mma_bf16(acc[mi][ni], aH[mi], bH[np][hh], bH[np][hh + 1]);
                    mma_bf16(acc[mi][ni], aH[mi], bL[np][hh], bL[np][hh + 1]);
                    mma_bf16(acc[mi][ni], aL[mi], bH[np][hh], bH[np][hh + 1]);
                }
            }
        }
    }

    // Epilogue
    #pragma unroll
    for (int mi = 0; mi < 4; mi++) {
        const size_t r0 = arow0 + wm * 64 + mi * 16 + (lane >> 2);
        #pragma unroll
        for (int ni = 0; ni < 4; ni++) {
            const int c = bx * 128 + wn * 32 + ni * 8 + (lane & 3) * 2;
            const float b0 = bias[c], b1 = bias[c + 1];
            float2 v0 = make_float2(acc[mi][ni][0] + b0, acc[mi][ni][1] + b1);
            float2 v1 = make_float2(acc[mi][ni][2] + b0, acc[mi][ni][3] + b1);
            *reinterpret_cast<float2*>(C + r0 * (size_t)N + c)       = v0;
            *reinterpret_cast<float2*>(C + (r0 + 8) * (size_t)N + c) = v1;
        }
    }
}

// ---------------------------------------------------------------------------
// fp32 -> bf16 hi/lo split
// ---------------------------------------------------------------------------
__global__ void split_rows(const float* __restrict__ X,
                           __nv_bfloat16* __restrict__ Xh,
                           __nv_bfloat16* __restrict__ Xl, size_t n)
{
    size_t i = ((size_t)blockIdx.x * blockDim.x + threadIdx.x) * 4;
    if (i >= n) return;
    float4 v = *reinterpret_cast<const float4*>(X + i);
    __nv_bfloat16 h0 = __float2bfloat16_rn(v.x);
    __nv_bfloat16 h1 = __float2bfloat16_rn(v.y);
    __nv_bfloat16 h2 = __float2bfloat16_rn(v.z);
    __nv_bfloat16 h3 = __float2bfloat16_rn(v.w);
    __nv_bfloat162 hA = __nv_bfloat162(h0, h1), hB = __nv_bfloat162(h2, h3);
    __nv_bfloat162 lA = __nv_bfloat162(__float2bfloat16_rn(v.x - __bfloat162float(h0)),
                                       __float2bfloat16_rn(v.y - __bfloat162float(h1)));
    __nv_bfloat162 lB = __nv_bfloat162(__float2bfloat16_rn(v.z - __bfloat162float(h2)),
                                       __float2bfloat16_rn(v.w - __bfloat162float(h3)));
    *reinterpret_cast<__nv_bfloat162*>(Xh + i)     = hA;
    *reinterpret_cast<__nv_bfloat162*>(Xh + i + 2) = hB;
    *reinterpret_cast<__nv_bfloat162*>(Xl + i)     = lA;
    *reinterpret_cast<__nv_bfloat162*>(Xl + i + 2) = lB;
}

// ---------------------------------------------------------------------------
// W[K,N] -> T[N,K] transpose + bf16 hi/lo split
// ---------------------------------------------------------------------------
__global__ void transpose_split(const float* __restrict__ W, int K, int N,
                                __nv_bfloat16* __restrict__ Th,
                                __nv_bfloat16* __restrict__ Tl)
{
    __shared__ float tile[32][33];
    int n0 = blockIdx.x * 32, k0 = blockIdx.y * 32;
    int tx = threadIdx.x, ty = threadIdx.y;
    #pragma unroll
    for (int i = 0; i < 32; i += 8)
        tile[ty + i][tx] = W[(size_t)(k0 + ty + i) * N + n0 + tx];
    __syncthreads();
    #pragma unroll
    for (int i = 0; i < 32; i += 8) {
        int nn = ty + i, kk = tx;
        float v = tile[kk][nn];
        __nv_bfloat16 h = __float2bfloat16_rn(v);
        Th[(size_t)(n0 + nn) * K + k0 + kk] = h;
        Tl[(size_t)(n0 + nn) * K + k0 + kk] = __float2bfloat16_rn(v - __bfloat162float(h));
    }
}

// ---------------------------------------------------------------------------
// LRU scan (3-phase chunked, 32 chunks x 64 steps)
// ---------------------------------------------------------------------------
__device__ __forceinline__ void chan_params(const float* __restrict__ nu_log,
                                            const float* __restrict__ theta_log,
                                            const float* __restrict__ gamma_log,
                                            int d, float& fr, float& fi, float& ga)
{
    float nu = expf(-expf(nu_log[d]));
    float th = expf(theta_log[d]);
    fr = nu * cosf(th);
    fi = nu * sinf(th);
    ga = expf(gamma_log[d]);
}

__global__ void scan_phase1(const float* __restrict__ nu_log,
                            const float* __restrict__ theta_log,
                            const float* __restrict__ gamma_log)
{
    int idx = blockIdx.x * blockDim.x + threadIdx.x;
    int d = idx % D_;
    int c = (idx / D_) % NCHUNK;
    int b = idx / (D_ * NCHUNK);

    float fr, fi, ga;
    chan_params(nu_log, theta_log, gamma_log, d, fr, fi, ga);

    const float* up = g_u + (size_t)(b * T_ + c * LCH) * N1;
    float hr = 0.f, hi = 0.f;
    #pragma unroll 4
    for (int t = 0; t < LCH; t++) {
        float vr = ga * up[(size_t)t * N1 + d];
        float vi = ga * up[(size_t)t * N1 + D_ + d];
        float nr = fr * hr - fi * hi + vr;
        float ni = fr * hi + fi * hr + vi;
        hr = nr; hi = ni;
    }
    g_cBr[idx] = hr;
    g_cBi[idx] = hi;
}

__global__ void scan_phase2(const float* __restrict__ nu_log,
                            const float* __restrict__ theta_log)
{
    int idx = blockIdx.x * blockDim.x + threadIdx.x;
    int d = idx % D_;
    int b = idx / D_;

    float nu = expf(-expf(nu_log[d]));
    float th = expf(theta_log[d]);
    float ar = nu * cosf(th);
    float ai = nu * sinf(th);
    // f^64 via 6 complex squarings
    #pragma unroll
    for (int s = 0; s < 6; s++) {
        float nr = ar * ar - ai * ai;
        float ni = 2.f * ar * ai;
        ar = nr; ai = ni;
    }

    float cr = 0.f, ci = 0.f;
    for (int c = 0; c < NCHUNK; c++) {
        int o = (b * NCHUNK + c) * D_ + d;
        g_carR[o] = cr;
        g_carI[o] = ci;
        float br = g_cBr[o], bi = g_cBi[o];
        float nr = ar * cr - ai * ci + br;
        float ni = ar * ci + ai * cr + bi;
        cr = nr; ci = ni;
    }
}

__global__ void scan_phase3(const float* __restrict__ nu_log,
                            const float* __restrict__ theta_log,
                            const float* __restrict__ gamma_log)
{
    int idx = blockIdx.x * blockDim.x + threadIdx.x;
    int d = idx % D_;
    int c = (idx / D_) % NCHUNK;
    int b = idx / (D_ * NCHUNK);

    float fr, fi, ga;
    chan_params(nu_log, theta_log, gamma_log, d, fr, fi, ga);

    int o = (b * NCHUNK + c) * D_ + d;
    float hr = g_carR[o], hi = g_carI[o];

    const float* up = g_u + (size_t)(b * T_ + c * LCH) * N1;
    float*       yp = g_y + (size_t)(b * T_ + c * LCH) * K2;

    #pragma unroll 4
    for (int t = 0; t < LCH; t++) {
        float vr = ga * up[(size_t)t * N1 + d];
        float vi = ga * up[(size_t)t * N1 + D_ + d];
        float o1 = up[(size_t)t * N1 + 2 * D_ + d];
        float o2 = up[(size_t)t * N1 + 3 * D_ + d];
        float nr = fr * hr - fi * hi + vr;
        float ni = fr * hi + fi * hr + vi;
        hr = nr; hi = ni;
        float s1 = o1 / (1.f + expf(-o1));
        float s2 = o2 / (1.f + expf(-o2));
        yp[(size_t)t * K2 + d]       = hr * s1;
        yp[(size_t)t * K2 + D_ + d]  = hi * s2;
    }
}

// ---------------------------------------------------------------------------
// LayerNorm(2048) fused with bf16 hi/lo split: g_y -> g_yh/g_yl
// ---------------------------------------------------------------------------
__global__ void ln_split_kernel(const float* __restrict__ ln_w,
                                const float* __restrict__ ln_b)
{
    const int row = blockIdx.x;
    const float* yp = g_y + (size_t)row * K2;
    __nv_bfloat16* yh = g_yh + (size_t)row * K2;
    __nv_bfloat16* yl = g_yl + (size_t)row * K2;

    float lsum = 0.f, lsq = 0.f;
    for (int i = threadIdx.x; i < K2; i += blockDim.x) {
        float v = yp[i];
        lsum += v;
        lsq  += v * v;
    }
    #pragma unroll
    for (int off = 16; off > 0; off >>= 1) {
        lsum += __shfl_xor_sync(0xFFFFFFFF, lsum, off);
        lsq  += __shfl_xor_sync(0xFFFFFFFF, lsq,  off);
    }
    __shared__ float s1[8], s2[8];
    int wid = threadIdx.x >> 5, lane = threadIdx.x & 31;
    if (lane == 0) { s1[wid] = lsum; s2[wid] = lsq; }
    __syncthreads();
    if (wid == 0) {
        float a = (lane < 8) ? s1[lane] : 0.f;
        float b = (lane < 8) ? s2[lane] : 0.f;
        #pragma unroll
        for (int off = 4; off > 0; off >>= 1) {
            a += __shfl_xor_sync(0xFFFFFFFF, a, off);
            b += __shfl_xor_sync(0xFFFFFFFF, b, off);
        }
        if (lane == 0) { s1[0] = a; s2[0] = b; }
    }
    __syncthreads();
    float mean = s1[0] / K2;
    float var  = s2[0] / K2 - mean * mean;
    float inv  = rsqrtf(var + 1e-5f);

    for (int i = threadIdx.x; i < K2; i += blockDim.x) {
        float v = (yp[i] - mean) * inv * ln_w[i] + ln_b[i];
        __nv_bfloat16 h = __float2bfloat16_rn(v);
        yh[i] = h;
        yl[i] = __float2bfloat16_rn(v - __bfloat162float(h));
    }
}

// ---------------------------------------------------------------------------
// Launch
// ---------------------------------------------------------------------------
extern "C" void kernel_launch(void* const* d_in, const int* in_sizes, int n_in,
                              void* d_out, int out_size)
{
    const float* x         = (const float*)d_in[0];
    const float* W_in      = (const float*)d_in[1];
    const float* b_in      = (const float*)d_in[2];
    const float* nu_log    = (const float*)d_in[3];
    const float* theta_log = (const float*)d_in[4];
    const float* gamma_log = (const float*)d_in[5];
    const float* ln_w      = (const float*)d_in[6];
    const float* ln_b      = (const float*)d_in[7];
    const float* W_out     = (const float*)d_in[8];
    const float* b_out     = (const float*)d_in[9];
    float* out = (float*)d_out;

    float *u_ptr;
    cudaGetSymbolAddress((void**)&u_ptr, g_u);
    __nv_bfloat16 *xh, *xl, *w1h, *w1l, *yh, *yl, *w2h, *w2l;
    cudaGetSymbolAddress((void**)&xh,  g_xh);
    cudaGetSymbolAddress((void**)&xl,  g_xl);
    cudaGetSymbolAddress((void**)&w1h, g_w1h);
    cudaGetSymbolAddress((void**)&w1l, g_w1l);
    cudaGetSymbolAddress((void**)&yh,  g_yh);
    cudaGetSymbolAddress((void**)&yl,  g_yl);
    cudaGetSymbolAddress((void**)&w2h, g_w2h);
    cudaGetSymbolAddress((void**)&w2l, g_w2l);

    cudaFuncSetAttribute(mma_gemm, cudaFuncAttributeMaxDynamicSharedMemorySize, GEMM_SMEM);

    // operand prep for GEMM1
    {
        size_t n = (size_t)M1 * K1;
        split_rows<<<(unsigned)((n / 4 + 255) / 256), 256>>>(x, xh, xl, n);
        dim3 g(N1 / 32, K1 / 32);
        transpose_split<<<g, dim3(32, 8)>>>(W_in, K1, N1, w1h, w1l);
    }
    // GEMM1: u = x @ W_in + b_in
    {
        int grid = (M1 / 128) * (N1 / 128);
        mma_gemm<<<grid, 256, GEMM_SMEM>>>(M1, N1, K1, xh, xl, w1h, w1l, b_in, u_ptr);
    }
    // Scan (3-phase)
    {
        int total = B_ * NCHUNK * D_;
        scan_phase1<<<total / 256, 256>>>(nu_log, theta_log, gamma_log);
        scan_phase2<<<(B_ * D_) / 256, 256>>>(nu_log, theta_log);
        scan_phase3<<<total / 256, 256>>>(nu_log, theta_log, gamma_log);
    }
    // LayerNorm + bf16 split fused
    ln_split_kernel<<<M1, 256>>>(ln_w, ln_b);

    // operand prep for GEMM2 (weights only; y already split)
    {
        dim3 g(N2 / 32, K2 / 32);
        transpose_split<<<g, dim3(32, 8)>>>(W_out, K2, N2, w2h, w2l);
    }
    // GEMM2: out = y @ W_out + b_out
    {
        int grid = (M1 / 128) * (N2 / 128);
        mma_gemm<<<grid, 256, GEMM_SMEM>>>(M1, N2, K2, yh, yl, w2h, w2l, b_out, out);
    }
}

// round 8
// speedup vs baseline: 3.0095x; 1.1057x over previous
#include <cuda_runtime.h>
#include <cuda_bf16.h>
#include <math.h>
#include <stdint.h>

// ---------------------------------------------------------------------------
// Problem constants
// ---------------------------------------------------------------------------
constexpr int B_  = 4;
constexpr int T_  = 2048;
constexpr int D_  = 1024;
constexpr int M1  = B_ * T_;        // 8192
constexpr int N1  = 4 * D_;         // 4096
constexpr int K1  = D_;             // 1024
constexpr int K2  = 2 * D_;         // 2048
constexpr int N2  = D_;             // 1024
constexpr int NCHUNK = 32;
constexpr int LCH = T_ / NCHUNK;    // 64

// ---------------------------------------------------------------------------
// Scratch (static device globals — no allocation allowed)
// ---------------------------------------------------------------------------
__device__ float g_u[(size_t)M1 * N1];
__device__ float g_y[(size_t)M1 * K2];
__device__ float g_cBr[B_ * NCHUNK * D_];
__device__ float g_cBi[B_ * NCHUNK * D_];
__device__ float g_carR[B_ * NCHUNK * D_];
__device__ float g_carI[B_ * NCHUNK * D_];

__device__ __nv_bfloat16 g_xh[(size_t)M1 * K1];
__device__ __nv_bfloat16 g_xl[(size_t)M1 * K1];
__device__ __nv_bfloat16 g_w1h[(size_t)N1 * K1];   // W_in^T  [4096,1024]
__device__ __nv_bfloat16 g_w1l[(size_t)N1 * K1];
__device__ __nv_bfloat16 g_yh[(size_t)M1 * K2];
__device__ __nv_bfloat16 g_yl[(size_t)M1 * K2];
__device__ __nv_bfloat16 g_w2h[(size_t)N2 * K2];   // W_out^T [1024,2048]
__device__ __nv_bfloat16 g_w2l[(size_t)N2 * K2];

// ---------------------------------------------------------------------------
// PTX helpers
// ---------------------------------------------------------------------------
__device__ __forceinline__ uint32_t smem_u32(const void* p) {
    uint32_t a;
    asm("{ .reg .u64 t; cvta.to.shared.u64 t, %1; cvt.u32.u64 %0, t; }"
        : "=r"(a) : "l"(p));
    return a;
}

__device__ __forceinline__ void cp16(uint32_t dst, const void* src) {
    asm volatile("cp.async.cg.shared.global [%0], [%1], 16;\n" :: "r"(dst), "l"(src) : "memory");
}
#define CP_COMMIT() asm volatile("cp.async.commit_group;" ::: "memory")

__device__ __forceinline__ void ldm_x4(uint32_t* r, uint32_t addr) {
    asm volatile("ldmatrix.sync.aligned.m8n8.x4.shared.b16 {%0,%1,%2,%3}, [%4];"
                 : "=r"(r[0]), "=r"(r[1]), "=r"(r[2]), "=r"(r[3]) : "r"(addr));
}

__device__ __forceinline__ void mma_bf16(float* d, const uint32_t* a, uint32_t b0, uint32_t b1) {
    asm volatile(
        "mma.sync.aligned.m16n8k16.row.col.f32.bf16.bf16.f32 "
        "{%0,%1,%2,%3}, {%4,%5,%6,%7}, {%8,%9}, {%0,%1,%2,%3};"
        : "+f"(d[0]), "+f"(d[1]), "+f"(d[2]), "+f"(d[3])
        : "r"(a[0]), "r"(a[1]), "r"(a[2]), "r"(a[3]), "r"(b0), "r"(b1));
}

// ---------------------------------------------------------------------------
// bf16-split MMA GEMM: C[M,N] = A[M,K] @ Bt[N,K]^T + bias
// 128x128 tile, BK=32, 8 warps (2m x 4n, warp tile 64x32).
// 3-stage cp.async ring, 2 CTAs/SM for latency hiding, grid swizzled.
// SMEM slot (32KB): Ah@0 Al@8K Bh@16K Bl@24K (each 128 rows x 64B, XOR swizzle)
// ---------------------------------------------------------------------------
constexpr int NSTAGE    = 3;
constexpr int SLOT      = 32768;
constexpr int GEMM_SMEM = NSTAGE * SLOT;   // 96 KB -> 2 CTAs/SM

__device__ __forceinline__ uint32_t sw_off(int row, int kch) {
    return (uint32_t)(row * 64 + ((kch ^ ((row >> 1) & 3)) << 4));
}

__global__ __launch_bounds__(256, 2)
void mma_gemm(int M, int N, int K,
              const __nv_bfloat16* __restrict__ Ah, const __nv_bfloat16* __restrict__ Al,
              const __nv_bfloat16* __restrict__ Bh, const __nv_bfloat16* __restrict__ Bl,
              const float* __restrict__ bias, float* __restrict__ C)
{
    extern __shared__ char smem[];
    const uint32_t sb = smem_u32(smem);
    const int tid  = threadIdx.x;
    const int lane = tid & 31;
    const int wid  = tid >> 5;
    const int wm   = wid & 1;
    const int wn   = wid >> 1;

    // grid swizzle: 8-row bands, column-minor inside band
    const int nbx  = N >> 7;
    const int lin  = blockIdx.x;
    const int band = lin / (8 * nbx);
    const int rem  = lin % (8 * nbx);
    const int by   = band * 8 + (rem & 7);
    const int bx   = rem >> 3;

    const size_t arow0 = (size_t)by * 128;
    const size_t brow0 = (size_t)bx * 128;
    const int S = K / 32;

    float acc[4][4][4];
    #pragma unroll
    for (int i = 0; i < 4; i++)
        #pragma unroll
        for (int j = 0; j < 4; j++)
            #pragma unroll
            for (int k = 0; k < 4; k++) acc[i][j][k] = 0.f;

    const int r0a = (tid + 0)   >> 2, c0a = (tid + 0)   & 3;
    const int r1a = (tid + 256) >> 2, c1a = (tid + 256) & 3;

    auto load_stage = [&](int s, int slot) {
        const uint32_t st = sb + (uint32_t)slot * (uint32_t)SLOT;
        const int k0 = s * 32;
        cp16(st +          sw_off(r0a, c0a), Ah + (arow0 + r0a) * (size_t)K + k0 + c0a * 8);
        cp16(st +          sw_off(r1a, c1a), Ah + (arow0 + r1a) * (size_t)K + k0 + c1a * 8);
        cp16(st + 8192u  + sw_off(r0a, c0a), Al + (arow0 + r0a) * (size_t)K + k0 + c0a * 8);
        cp16(st + 8192u  + sw_off(r1a, c1a), Al + (arow0 + r1a) * (size_t)K + k0 + c1a * 8);
        cp16(st + 16384u + sw_off(r0a, c0a), Bh + (brow0 + r0a) * (size_t)K + k0 + c0a * 8);
        cp16(st + 16384u + sw_off(r1a, c1a), Bh + (brow0 + r1a) * (size_t)K + k0 + c1a * 8);
        cp16(st + 24576u + sw_off(r0a, c0a), Bl + (brow0 + r0a) * (size_t)K + k0 + c0a * 8);
        cp16(st + 24576u + sw_off(r1a, c1a), Bl + (brow0 + r1a) * (size_t)K + k0 + c1a * 8);
    };

    const int sub = lane >> 3;
    const int r8  = lane & 7;

    // preload first 2 stages (one commit group each)
    load_stage(0, 0); CP_COMMIT();
    load_stage(1, 1); CP_COMMIT();

    int slot_c = 0;   // compute slot
    int slot_l = 2;   // next load slot
    for (int s = 0; s < S; s++) {
        // exactly one group committed per iteration -> wait 1 == stage s ready
        asm volatile("cp.async.wait_group 1;" ::: "memory");
        __syncthreads();

        if (s + 2 < S) load_stage(s + 2, slot_l);
        CP_COMMIT();

        const uint32_t st = sb + (uint32_t)slot_c * (uint32_t)SLOT;
        #pragma unroll
        for (int ks = 0; ks < 2; ks++) {
            uint32_t aH[4][4], aL[4][4], bH[2][4], bL[2][4];
            #pragma unroll
            for (int mi = 0; mi < 4; mi++) {
                const int mrow = wm * 64 + mi * 16 + (sub & 1) * 8 + r8;
                const int kch  = ks * 2 + (sub >> 1);
                ldm_x4(aH[mi], st +         sw_off(mrow, kch));
                ldm_x4(aL[mi], st + 8192u + sw_off(mrow, kch));
            }
            #pragma unroll
            for (int np = 0; np < 2; np++) {
                const int nrow = wn * 32 + np * 16 + (sub >> 1) * 8 + r8;
                const int kch  = ks * 2 + (sub & 1);
                ldm_x4(bH[np], st + 16384u + sw_off(nrow, kch));
                ldm_x4(bL[np], st + 24576u + sw_off(nrow, kch));
            }
            #pragma unroll
            for (int mi = 0; mi < 4; mi++) {
                #pragma unroll
                for (int ni = 0; ni < 4; ni++) {
                    const int np = ni >> 1, hh = (ni & 1) * 2;
                    mma_bf16(acc[mi][ni], aH[mi], bH[np][hh], bH[np][hh + 1]);
                    mma_bf16(acc[mi][ni], aH[mi], bL[np][hh], bL[np][hh + 1]);
                    mma_bf16(acc[mi][ni], aL[mi], bH[np][hh], bH[np][hh + 1]);
                }
            }
        }
        // advance ring
        slot_c = (slot_c == 2) ? 0 : slot_c + 1;
        slot_l = (slot_l == 2) ? 0 : slot_l + 1;
        __syncthreads();
    }

    // Epilogue
    #pragma unroll
    for (int mi = 0; mi < 4; mi++) {
        const size_t r0 = arow0 + wm * 64 + mi * 16 + (lane >> 2);
        #pragma unroll
        for (int ni = 0; ni < 4; ni++) {
            const int c = bx * 128 + wn * 32 + ni * 8 + (lane & 3) * 2;
            const float b0 = bias[c], b1 = bias[c + 1];
            float2 v0 = make_float2(acc[mi][ni][0] + b0, acc[mi][ni][1] + b1);
            float2 v1 = make_float2(acc[mi][ni][2] + b0, acc[mi][ni][3] + b1);
            *reinterpret_cast<float2*>(C + r0 * (size_t)N + c)       = v0;
            *reinterpret_cast<float2*>(C + (r0 + 8) * (size_t)N + c) = v1;
        }
    }
}

// ---------------------------------------------------------------------------
// fp32 -> bf16 hi/lo split
// ---------------------------------------------------------------------------
__global__ void split_rows(const float* __restrict__ X,
                           __nv_bfloat16* __restrict__ Xh,
                           __nv_bfloat16* __restrict__ Xl, size_t n)
{
    size_t i = ((size_t)blockIdx.x * blockDim.x + threadIdx.x) * 4;
    if (i >= n) return;
    float4 v = *reinterpret_cast<const float4*>(X + i);
    __nv_bfloat16 h0 = __float2bfloat16_rn(v.x);
    __nv_bfloat16 h1 = __float2bfloat16_rn(v.y);
    __nv_bfloat16 h2 = __float2bfloat16_rn(v.z);
    __nv_bfloat16 h3 = __float2bfloat16_rn(v.w);
    __nv_bfloat162 hA = __nv_bfloat162(h0, h1), hB = __nv_bfloat162(h2, h3);
    __nv_bfloat162 lA = __nv_bfloat162(__float2bfloat16_rn(v.x - __bfloat162float(h0)),
                                       __float2bfloat16_rn(v.y - __bfloat162float(h1)));
    __nv_bfloat162 lB = __nv_bfloat162(__float2bfloat16_rn(v.z - __bfloat162float(h2)),
                                       __float2bfloat16_rn(v.w - __bfloat162float(h3)));
    *reinterpret_cast<__nv_bfloat162*>(Xh + i)     = hA;
    *reinterpret_cast<__nv_bfloat162*>(Xh + i + 2) = hB;
    *reinterpret_cast<__nv_bfloat162*>(Xl + i)     = lA;
    *reinterpret_cast<__nv_bfloat162*>(Xl + i + 2) = lB;
}

// ---------------------------------------------------------------------------
// W[K,N] -> T[N,K] transpose + bf16 hi/lo split
// ---------------------------------------------------------------------------
__global__ void transpose_split(const float* __restrict__ W, int K, int N,
                                __nv_bfloat16* __restrict__ Th,
                                __nv_bfloat16* __restrict__ Tl)
{
    __shared__ float tile[32][33];
    int n0 = blockIdx.x * 32, k0 = blockIdx.y * 32;
    int tx = threadIdx.x, ty = threadIdx.y;
    #pragma unroll
    for (int i = 0; i < 32; i += 8)
        tile[ty + i][tx] = W[(size_t)(k0 + ty + i) * N + n0 + tx];
    __syncthreads();
    #pragma unroll
    for (int i = 0; i < 32; i += 8) {
        int nn = ty + i, kk = tx;
        float v = tile[kk][nn];
        __nv_bfloat16 h = __float2bfloat16_rn(v);
        Th[(size_t)(n0 + nn) * K + k0 + kk] = h;
        Tl[(size_t)(n0 + nn) * K + k0 + kk] = __float2bfloat16_rn(v - __bfloat162float(h));
    }
}

// ---------------------------------------------------------------------------
// LRU scan (3-phase chunked, 32 chunks x 64 steps)
// ---------------------------------------------------------------------------
__device__ __forceinline__ void chan_params(const float* __restrict__ nu_log,
                                            const float* __restrict__ theta_log,
                                            const float* __restrict__ gamma_log,
                                            int d, float& fr, float& fi, float& ga)
{
    float nu = expf(-expf(nu_log[d]));
    float th = expf(theta_log[d]);
    fr = nu * cosf(th);
    fi = nu * sinf(th);
    ga = expf(gamma_log[d]);
}

__global__ void scan_phase1(const float* __restrict__ nu_log,
                            const float* __restrict__ theta_log,
                            const float* __restrict__ gamma_log)
{
    int idx = blockIdx.x * blockDim.x + threadIdx.x;
    int d = idx % D_;
    int c = (idx / D_) % NCHUNK;
    int b = idx / (D_ * NCHUNK);

    float fr, fi, ga;
    chan_params(nu_log, theta_log, gamma_log, d, fr, fi, ga);

    const float* up = g_u + (size_t)(b * T_ + c * LCH) * N1;
    float hr = 0.f, hi = 0.f;
    #pragma unroll 4
    for (int t = 0; t < LCH; t++) {
        float vr = ga * up[(size_t)t * N1 + d];
        float vi = ga * up[(size_t)t * N1 + D_ + d];
        float nr = fr * hr - fi * hi + vr;
        float ni = fr * hi + fi * hr + vi;
        hr = nr; hi = ni;
    }
    g_cBr[idx] = hr;
    g_cBi[idx] = hi;
}

__global__ void scan_phase2(const float* __restrict__ nu_log,
                            const float* __restrict__ theta_log)
{
    int idx = blockIdx.x * blockDim.x + threadIdx.x;
    int d = idx % D_;
    int b = idx / D_;

    float nu = expf(-expf(nu_log[d]));
    float th = expf(theta_log[d]);
    float ar = nu * cosf(th);
    float ai = nu * sinf(th);
    // f^64 via 6 complex squarings
    #pragma unroll
    for (int s = 0; s < 6; s++) {
        float nr = ar * ar - ai * ai;
        float ni = 2.f * ar * ai;
        ar = nr; ai = ni;
    }

    float cr = 0.f, ci = 0.f;
    for (int c = 0; c < NCHUNK; c++) {
        int o = (b * NCHUNK + c) * D_ + d;
        g_carR[o] = cr;
        g_carI[o] = ci;
        float br = g_cBr[o], bi = g_cBi[o];
        float nr = ar * cr - ai * ci + br;
        float ni = ar * ci + ai * cr + bi;
        cr = nr; ci = ni;
    }
}

__global__ void scan_phase3(const float* __restrict__ nu_log,
                            const float* __restrict__ theta_log,
                            const float* __restrict__ gamma_log)
{
    int idx = blockIdx.x * blockDim.x + threadIdx.x;
    int d = idx % D_;
    int c = (idx / D_) % NCHUNK;
    int b = idx / (D_ * NCHUNK);

    float fr, fi, ga;
    chan_params(nu_log, theta_log, gamma_log, d, fr, fi, ga);

    int o = (b * NCHUNK + c) * D_ + d;
    float hr = g_carR[o], hi = g_carI[o];

    const float* up = g_u + (size_t)(b * T_ + c * LCH) * N1;
    float*       yp = g_y + (size_t)(b * T_ + c * LCH) * K2;

    #pragma unroll 4
    for (int t = 0; t < LCH; t++) {
        float vr = ga * up[(size_t)t * N1 + d];
        float vi = ga * up[(size_t)t * N1 + D_ + d];
        float o1 = up[(size_t)t * N1 + 2 * D_ + d];
        float o2 = up[(size_t)t * N1 + 3 * D_ + d];
        float nr = fr * hr - fi * hi + vr;
        float ni = fr * hi + fi * hr + vi;
        hr = nr; hi = ni;
        float s1 = o1 / (1.f + expf(-o1));
        float s2 = o2 / (1.f + expf(-o2));
        yp[(size_t)t * K2 + d]       = hr * s1;
        yp[(size_t)t * K2 + D_ + d]  = hi * s2;
    }
}

// ---------------------------------------------------------------------------
// LayerNorm(2048) fused with bf16 hi/lo split: g_y -> g_yh/g_yl
// ---------------------------------------------------------------------------
__global__ void ln_split_kernel(const float* __restrict__ ln_w,
                                const float* __restrict__ ln_b)
{
    const int row = blockIdx.x;
    const float* yp = g_y + (size_t)row * K2;
    __nv_bfloat16* yh = g_yh + (size_t)row * K2;
    __nv_bfloat16* yl = g_yl + (size_t)row * K2;

    float lsum = 0.f, lsq = 0.f;
    for (int i = threadIdx.x; i < K2; i += blockDim.x) {
        float v = yp[i];
        lsum += v;
        lsq  += v * v;
    }
    #pragma unroll
    for (int off = 16; off > 0; off >>= 1) {
        lsum += __shfl_xor_sync(0xFFFFFFFF, lsum, off);
        lsq  += __shfl_xor_sync(0xFFFFFFFF, lsq,  off);
    }
    __shared__ float s1[8], s2[8];
    int wid = threadIdx.x >> 5, lane = threadIdx.x & 31;
    if (lane == 0) { s1[wid] = lsum; s2[wid] = lsq; }
    __syncthreads();
    if (wid == 0) {
        float a = (lane < 8) ? s1[lane] : 0.f;
        float b = (lane < 8) ? s2[lane] : 0.f;
        #pragma unroll
        for (int off = 4; off > 0; off >>= 1) {
            a += __shfl_xor_sync(0xFFFFFFFF, a, off);
            b += __shfl_xor_sync(0xFFFFFFFF, b, off);
        }
        if (lane == 0) { s1[0] = a; s2[0] = b; }
    }
    __syncthreads();
    float mean = s1[0] / K2;
    float var  = s2[0] / K2 - mean * mean;
    float inv  = rsqrtf(var + 1e-5f);

    for (int i = threadIdx.x; i < K2; i += blockDim.x) {
        float v = (yp[i] - mean) * inv * ln_w[i] + ln_b[i];
        __nv_bfloat16 h = __float2bfloat16_rn(v);
        yh[i] = h;
        yl[i] = __float2bfloat16_rn(v - __bfloat162float(h));
    }
}

// ---------------------------------------------------------------------------
// Launch
// ---------------------------------------------------------------------------
extern "C" void kernel_launch(void* const* d_in, const int* in_sizes, int n_in,
                              void* d_out, int out_size)
{
    const float* x         = (const float*)d_in[0];
    const float* W_in      = (const float*)d_in[1];
    const float* b_in      = (const float*)d_in[2];
    const float* nu_log    = (const float*)d_in[3];
    const float* theta_log = (const float*)d_in[4];
    const float* gamma_log = (const float*)d_in[5];
    const float* ln_w      = (const float*)d_in[6];
    const float* ln_b      = (const float*)d_in[7];
    const float* W_out     = (const float*)d_in[8];
    const float* b_out     = (const float*)d_in[9];
    float* out = (float*)d_out;

    float *u_ptr;
    cudaGetSymbolAddress((void**)&u_ptr, g_u);
    __nv_bfloat16 *xh, *xl, *w1h, *w1l, *yh, *yl, *w2h, *w2l;
    cudaGetSymbolAddress((void**)&xh,  g_xh);
    cudaGetSymbolAddress((void**)&xl,  g_xl);
    cudaGetSymbolAddress((void**)&w1h, g_w1h);
    cudaGetSymbolAddress((void**)&w1l, g_w1l);
    cudaGetSymbolAddress((void**)&yh,  g_yh);
    cudaGetSymbolAddress((void**)&yl,  g_yl);
    cudaGetSymbolAddress((void**)&w2h, g_w2h);
    cudaGetSymbolAddress((void**)&w2l, g_w2l);

    cudaFuncSetAttribute(mma_gemm, cudaFuncAttributeMaxDynamicSharedMemorySize, GEMM_SMEM);

    // operand prep for GEMM1
    {
        size_t n = (size_t)M1 * K1;
        split_rows<<<(unsigned)((n / 4 + 255) / 256), 256>>>(x, xh, xl, n);
        dim3 g(N1 / 32, K1 / 32);
        transpose_split<<<g, dim3(32, 8)>>>(W_in, K1, N1, w1h, w1l);
    }
    // GEMM1: u = x @ W_in + b_in
    {
        int grid = (M1 / 128) * (N1 / 128);
        mma_gemm<<<grid, 256, GEMM_SMEM>>>(M1, N1, K1, xh, xl, w1h, w1l, b_in, u_ptr);
    }
    // Scan (3-phase)
    {
        int total = B_ * NCHUNK * D_;
        scan_phase1<<<total / 256, 256>>>(nu_log, theta_log, gamma_log);
        scan_phase2<<<(B_ * D_) / 256, 256>>>(nu_log, theta_log);
        scan_phase3<<<total / 256, 256>>>(nu_log, theta_log, gamma_log);
    }
    // LayerNorm + bf16 split fused
    ln_split_kernel<<<M1, 256>>>(ln_w, ln_b);

    // operand prep for GEMM2 (weights only; y already split)
    {
        dim3 g(N2 / 32, K2 / 32);
        transpose_split<<<g, dim3(32, 8)>>>(W_out, K2, N2, w2h, w2l);
    }
    // GEMM2: out = y @ W_out + b_out
    {
        int grid = (M1 / 128) * (N2 / 128);
        mma_gemm<<<grid, 256, GEMM_SMEM>>>(M1, N2, K2, yh, yl, w2h, w2l, b_out, out);
    }
}